// round 8
// baseline (speedup 1.0000x reference)
#include <cuda_runtime.h>
#include <cuda_bf16.h>

#define IMG    256
#define TS     8                  // raster tile = 8x8 pixels
#define TGRID  (IMG/TS)           // 32
#define NTILES (TGRID*TGRID)      // 1024 per batch
#define BMAX   2
#define NPIX   (IMG*IMG)
#define FCAP   8192               // B*F total faces
#define TCAP   2048               // per-tile candidate capacity
#define NEARP  0.1f
#define FARP   100.0f

// Per-face precomputed data
// g_edge[f*3+e] = (xa, ya, xb-xa, yb-ya)
// g_ins [f*3+k] = (inv[k][0], inv[k][1], inv[k][2], 1/z_k)
__device__ float4 g_edge[FCAP*3];
__device__ float4 g_ins [FCAP*3];
// Per-tile candidate lists (built face-parallel in prep)
__device__ int g_tileCnt[BMAX*NTILES];
__device__ int g_list[(size_t)BMAX*NTILES*TCAP];

__global__ void zero_kernel(int n) {
    int i = blockIdx.x * blockDim.x + threadIdx.x;
    if (i < n) g_tileCnt[i] = 0;
}

__global__ void prep_kernel(const float* __restrict__ faces, int F, int BF) {
    int gf = blockIdx.x * blockDim.x + threadIdx.x;
    if (gf >= BF) return;
    int b  = gf / F;
    int fl = gf - b * F;
    const float* v = faces + (size_t)gf * 9;
    float x0 = v[0], y0 = v[1], z0 = v[2];
    float x1 = v[3], y1 = v[4], z1 = v[5];
    float x2 = v[6], y2 = v[7], z2 = v[8];

    g_edge[gf*3+0] = make_float4(x0, y0, x1 - x0, y1 - y0);
    g_edge[gf*3+1] = make_float4(x1, y1, x2 - x1, y2 - y1);
    g_edge[gf*3+2] = make_float4(x2, y2, x0 - x2, y0 - y2);

    // det exactly as reference, then clamp away from 0
    float det = x2*(y0 - y1) + x0*(y1 - y2) + x1*(y2 - y0);
    det = (det >= 0.f) ? fmaxf(det, 1e-10f) : fminf(det, -1e-10f);

    g_ins[gf*3+0] = make_float4(__fdiv_rn(y1 - y2, det), __fdiv_rn(x2 - x1, det),
                                __fdiv_rn(x1*y2 - x2*y1, det), __frcp_rn(z0));
    g_ins[gf*3+1] = make_float4(__fdiv_rn(y2 - y0, det), __fdiv_rn(x0 - x2, det),
                                __fdiv_rn(x2*y0 - x0*y2, det), __frcp_rn(z1));
    g_ins[gf*3+2] = make_float4(__fdiv_rn(y0 - y1, det), __fdiv_rn(x1 - x0, det),
                                __fdiv_rn(x0*y1 - x1*y0, det), __frcp_rn(z2));

    // Conservative pixel-index bbox (+1px margin each side)
    float xmn = fminf(x0, fminf(x1, x2)) - 1e-4f;
    float xmx = fmaxf(x0, fmaxf(x1, x2)) + 1e-4f;
    float ymn = fminf(y0, fminf(y1, y2)) - 1e-4f;
    float ymx = fmaxf(y0, fmaxf(y1, y2)) + 1e-4f;
    // pixel center x_j = (2j+1-256)/256  (increasing in j)
    // pixel center y_i = -(2i+1-256)/256 (decreasing in i)
    int jlo = (int)ceilf ((xmn * 256.f + 255.f) * 0.5f) - 1;
    int jhi = (int)floorf((xmx * 256.f + 255.f) * 0.5f) + 1;
    int ilo = (int)ceilf ((255.f - ymx * 256.f) * 0.5f) - 1;
    int ihi = (int)floorf((255.f - ymn * 256.f) * 0.5f) + 1;
    if (jhi < 0 || jlo > IMG-1 || ihi < 0 || ilo > IMG-1) return;
    jlo = max(jlo, 0); jhi = min(jhi, IMG-1);
    ilo = max(ilo, 0); ihi = min(ihi, IMG-1);
    int txlo = jlo >> 3, txhi = jhi >> 3;
    int tylo = ilo >> 3, tyhi = ihi >> 3;
    int tb = b * NTILES;
    for (int ty = tylo; ty <= tyhi; ty++) {
        for (int tx = txlo; tx <= txhi; tx++) {
            int t = tb + ty * TGRID + tx;
            int pos = atomicAdd(&g_tileCnt[t], 1);
            if (pos < TCAP) g_list[(size_t)t * TCAP + pos] = fl;
        }
    }
}

__global__ __launch_bounds__(64)
void raster_kernel(const float* __restrict__ tex, float* __restrict__ out,
                   int F, int B) {
    int b  = blockIdx.z;
    int tx = blockIdx.x, ty = blockIdx.y;
    int j  = tx * TS + (threadIdx.x & 7);
    int i  = ty * TS + (threadIdx.x >> 3);

    float xp = (2.f * j + 1.f - IMG) * (1.f / IMG);
    float yp = -((2.f * i + 1.f - IMG) * (1.f / IMG));

    int t = b * NTILES + ty * TGRID + tx;
    int nc = min(g_tileCnt[t], TCAP);
    const int* lst = g_list + (size_t)t * TCAP;
    int base = b * F;

    float bestZ = FARP;
    int   bestF = -1;
    float bw0 = 0.f, bw1 = 0.f, bw2 = 0.f;

    for (int c = 0; c < nc; c++) {
        int f = __ldg(lst + c);
        const float4* E = g_edge + (size_t)(base + f) * 3;
        float4 e0 = __ldg(E), e1 = __ldg(E + 1), e2 = __ldg(E + 2);
        // edge = (yp-ya)*(xb-xa) - (xp-xa)*(yb-ya) — exact reference-shaped fmaf
        float v0 = fmaf(yp - e0.y, e0.z, -((xp - e0.x) * e0.w));
        float v1 = fmaf(yp - e1.y, e1.z, -((xp - e1.x) * e1.w));
        float v2 = fmaf(yp - e2.y, e2.z, -((xp - e2.x) * e2.w));
        if (v0 >= 0.f && v1 >= 0.f && v2 >= 0.f) {
            const float4* I = g_ins + (size_t)(base + f) * 3;
            float4 r0 = __ldg(I), r1 = __ldg(I + 1), r2 = __ldg(I + 2);
            float w0 = fmaf(r0.x, xp, fmaf(r0.y, yp, r0.z));
            float w1 = fmaf(r1.x, xp, fmaf(r1.y, yp, r1.z));
            float w2 = fmaf(r2.x, xp, fmaf(r2.y, yp, r2.z));
            w0 = fminf(fmaxf(w0, 0.f), 1.f);
            w1 = fminf(fmaxf(w1, 0.f), 1.f);
            w2 = fminf(fmaxf(w2, 0.f), 1.f);
            float rs = __frcp_rn(fmaxf((w0 + w1) + w2, 1e-10f));
            w0 *= rs; w1 *= rs; w2 *= rs;
            float izp = fmaf(w0, r0.w, fmaf(w1, r1.w, w2 * r2.w));
            float zp  = __frcp_rn(fmaxf(izp, 1e-10f));
            if (zp > NEARP && zp < FARP) {
                if (zp < bestZ || (zp == bestZ && f < bestF)) {
                    bestZ = zp; bestF = f;
                    bw0 = w0; bw1 = w1; bw2 = w2;
                }
            }
        }
    }

    // Shade winner: trilinear sample of 4x4x4x3 texture
    float cr = 0.f, cg = 0.f, cb = 0.f, alpha = 0.f;
    if (bestF >= 0) {
        alpha = 1.f;
        const float4* I = g_ins + (size_t)(base + bestF) * 3;
        float rz0 = __ldg(I).w, rz1 = __ldg(I + 1).w, rz2 = __ldg(I + 2).w;
        // tif = clip(w*(T-1)*(zp/fz), 0, T-1-EPS), T=4
        float t0 = fminf(fmaxf((bw0 * 3.f) * (bestZ * rz0), 0.f), 2.999f);
        float t1 = fminf(fmaxf((bw1 * 3.f) * (bestZ * rz1), 0.f), 2.999f);
        float t2 = fminf(fmaxf((bw2 * 3.f) * (bestZ * rz2), 0.f), 2.999f);
        int l0 = (int)t0, l1 = (int)t1, l2 = (int)t2;
        float f0 = t0 - (float)l0, f1 = t1 - (float)l1, f2 = t2 - (float)l2;
        const float* tb = tex + (size_t)(base + bestF) * 192;  // 4*4*4*3
        #pragma unroll
        for (int pn = 0; pn < 8; pn++) {
            int b0 = pn & 1, b1 = (pn >> 1) & 1, b2 = (pn >> 2) & 1;
            float wc = (b0 ? f0 : 1.f - f0) * (b1 ? f1 : 1.f - f1) * (b2 ? f2 : 1.f - f2);
            const float* tp = tb + (size_t)((((l0 + b0) * 4 + (l1 + b1)) * 4 + (l2 + b2)) * 3);
            cr = fmaf(wc, __ldg(tp + 0), cr);
            cg = fmaf(wc, __ldg(tp + 1), cg);
            cb = fmaf(wc, __ldg(tp + 2), cb);
        }
    }

    // Output: [rgb (B,256,256,3)] [alpha (B,256,256)] [zp (B,256,256)]
    int p = i * IMG + j;
    size_t P = NPIX;
    float* orgb = out + ((size_t)b * P + p) * 3;
    orgb[0] = cr; orgb[1] = cg; orgb[2] = cb;
    out[(size_t)B * P * 3 + (size_t)b * P + p] = alpha;
    out[(size_t)B * P * 3 + (size_t)B * P + (size_t)b * P + p] = bestZ;
}

extern "C" void kernel_launch(void* const* d_in, const int* in_sizes, int n_in,
                              void* d_out, int out_size) {
    const float* faces = (const float*)d_in[0];   // (B,F,3,3) f32
    const float* tex   = (const float*)d_in[1];   // (B,F,4,4,4,3) f32
    float* out = (float*)d_out;

    int BF = in_sizes[0] / 9;
    int B  = out_size / (NPIX * 5);
    int F  = BF / B;

    int nt = B * NTILES;
    zero_kernel<<<(nt + 255) / 256, 256>>>(nt);
    prep_kernel<<<(BF + 255) / 256, 256>>>(faces, F, BF);
    dim3 grid(TGRID, TGRID, B);
    raster_kernel<<<grid, 64>>>(tex, out, F, B);
}

// round 13
// speedup vs baseline: 2.0614x; 2.0614x over previous
#include <cuda_runtime.h>
#include <cuda_bf16.h>

#define IMG   256
#define TILE  16
#define NPIX  (IMG*IMG)
#define FCAP  8192          // B*F = 2*4096 faces total
#define NEARP 0.1f
#define FARP  100.0f

// Per-face precomputed data (prep kernel -> raster kernel)
// g_edge[f*3+e] = (xa, ya, xb-xa, yb-ya) for edge e of face f
// g_ins [f*3+k] = (inv[k][0], inv[k][1], inv[k][2], 1/z_k)
// g_bbox[f]     = (xmin, xmax, ymin, ymax) conservative
__device__ float4 g_edge[FCAP*3];
__device__ float4 g_ins [FCAP*3];
__device__ float4 g_bbox[FCAP];

__global__ void prep_kernel(const float* __restrict__ faces, int BF) {
    int f = blockIdx.x * blockDim.x + threadIdx.x;
    if (f >= BF) return;
    const float* v = faces + (size_t)f * 9;
    float x0 = v[0], y0 = v[1], z0 = v[2];
    float x1 = v[3], y1 = v[4], z1 = v[5];
    float x2 = v[6], y2 = v[7], z2 = v[8];

    g_edge[f*3+0] = make_float4(x0, y0, x1 - x0, y1 - y0);
    g_edge[f*3+1] = make_float4(x1, y1, x2 - x1, y2 - y1);
    g_edge[f*3+2] = make_float4(x2, y2, x0 - x2, y0 - y2);

    // det exactly as reference, then clamp away from 0
    float det = x2*(y0 - y1) + x0*(y1 - y2) + x1*(y2 - y0);
    det = (det >= 0.f) ? fmaxf(det, 1e-10f) : fminf(det, -1e-10f);

    g_ins[f*3+0] = make_float4(__fdiv_rn(y1 - y2, det), __fdiv_rn(x2 - x1, det),
                               __fdiv_rn(x1*y2 - x2*y1, det), __frcp_rn(z0));
    g_ins[f*3+1] = make_float4(__fdiv_rn(y2 - y0, det), __fdiv_rn(x0 - x2, det),
                               __fdiv_rn(x2*y0 - x0*y2, det), __frcp_rn(z1));
    g_ins[f*3+2] = make_float4(__fdiv_rn(y0 - y1, det), __fdiv_rn(x1 - x0, det),
                               __fdiv_rn(x0*y1 - x1*y0, det), __frcp_rn(z2));

    float xmn = fminf(x0, fminf(x1, x2)) - 1e-4f;
    float xmx = fmaxf(x0, fmaxf(x1, x2)) + 1e-4f;
    float ymn = fminf(y0, fminf(y1, y2)) - 1e-4f;
    float ymx = fmaxf(y0, fmaxf(y1, y2)) + 1e-4f;
    g_bbox[f] = make_float4(xmn, xmx, ymn, ymx);
}

// Block = one 16x16 pixel tile, 512 threads = (256 pixels) x (2 candidate
// subsets). Thread (pix, s) tests candidates c = s, s+2, ... and the two
// partial winners are merged via smem with (z, face) lexicographic order —
// identical result to a serial scan.
__global__ __launch_bounds__(512)
void raster_kernel(const float* __restrict__ tex, float* __restrict__ out,
                   int F, int B) {
    __shared__ int   sCand[2048];
    __shared__ int   sCount;
    __shared__ float sZ [256];
    __shared__ int   sFc[256];
    __shared__ float sW0[256], sW1[256], sW2[256];

    int b  = blockIdx.z;
    int tx = blockIdx.x, ty = blockIdx.y;
    int tid = threadIdx.x;
    int pix = tid & 255;          // 0..255 pixel within tile
    int s   = tid >> 8;           // 0/1 candidate subset
    int j  = tx * TILE + (pix & 15);
    int i  = ty * TILE + (pix >> 4);

    // Pixel center (exact: integer numerator, /256 exact)
    float xp = (2.f * j + 1.f - IMG) * (1.f / IMG);
    float yp = -((2.f * i + 1.f - IMG) * (1.f / IMG));

    // Tile pixel-center extents for bbox culling
    float xlo = (2.f * (tx * TILE) + 1.f - IMG) * (1.f / IMG);
    float xhi = xlo + (2.f * (TILE - 1)) * (1.f / IMG);
    float yhi = -((2.f * (ty * TILE) + 1.f - IMG) * (1.f / IMG));
    float ylo = yhi - (2.f * (TILE - 1)) * (1.f / IMG);

    if (tid == 0) sCount = 0;
    __syncthreads();

    int base = b * F;
    // Bin: cull faces by bbox vs tile extent into smem candidate list.
    for (int f = tid; f < F; f += 512) {
        float4 bb = g_bbox[base + f];
        if (bb.x <= xhi && bb.y >= xlo && bb.z <= yhi && bb.w >= ylo) {
            sCand[atomicAdd(&sCount, 1)] = f;
        }
    }
    __syncthreads();
    int nc = sCount;

    float bestZ = FARP;
    int   bestF = -1;
    float bw0 = 0.f, bw1 = 0.f, bw2 = 0.f;

    for (int c = s; c < nc; c += 2) {
        int f = sCand[c];
        int idx3 = (base + f) * 3;
        const float4* E = g_edge + idx3;
        float4 e0 = __ldg(E), e1 = __ldg(E + 1), e2 = __ldg(E + 2);
        // edge = (yp-ya)*(xb-xa) - (xp-xa)*(yb-ya) — exact reference-shaped fmaf
        float v0 = fmaf(yp - e0.y, e0.z, -((xp - e0.x) * e0.w));
        float v1 = fmaf(yp - e1.y, e1.z, -((xp - e1.x) * e1.w));
        float v2 = fmaf(yp - e2.y, e2.z, -((xp - e2.x) * e2.w));
        if (v0 >= 0.f && v1 >= 0.f && v2 >= 0.f) {
            const float4* I = g_ins + idx3;
            float4 r0 = __ldg(I), r1 = __ldg(I + 1), r2 = __ldg(I + 2);
            float w0 = fmaf(r0.x, xp, fmaf(r0.y, yp, r0.z));
            float w1 = fmaf(r1.x, xp, fmaf(r1.y, yp, r1.z));
            float w2 = fmaf(r2.x, xp, fmaf(r2.y, yp, r2.z));
            w0 = fminf(fmaxf(w0, 0.f), 1.f);
            w1 = fminf(fmaxf(w1, 0.f), 1.f);
            w2 = fminf(fmaxf(w2, 0.f), 1.f);
            float rs = __frcp_rn(fmaxf((w0 + w1) + w2, 1e-10f));
            w0 *= rs; w1 *= rs; w2 *= rs;
            float izp = fmaf(w0, r0.w, fmaf(w1, r1.w, w2 * r2.w));
            float zp  = __frcp_rn(fmaxf(izp, 1e-10f));
            if (zp > NEARP && zp < FARP) {
                if (zp < bestZ || (zp == bestZ && f < bestF)) {
                    bestZ = zp; bestF = f;
                    bw0 = w0; bw1 = w1; bw2 = w2;
                }
            }
        }
    }

    // Merge subset-1 partials into subset-0 threads.
    if (s == 1) {
        sZ[pix] = bestZ; sFc[pix] = bestF;
        sW0[pix] = bw0; sW1[pix] = bw1; sW2[pix] = bw2;
    }
    __syncthreads();
    if (s == 1) return;

    {
        float z1 = sZ[pix]; int f1 = sFc[pix];
        // valid partials always have z < FARP and f >= 0; empty = (FARP, -1)
        if (z1 < bestZ || (z1 == bestZ && f1 >= 0 && (unsigned)f1 < (unsigned)bestF)) {
            bestZ = z1; bestF = f1;
            bw0 = sW0[pix]; bw1 = sW1[pix]; bw2 = sW2[pix];
        }
    }

    // Shade winner: trilinear sample of 4x4x4x3 texture
    float cr = 0.f, cg = 0.f, cb = 0.f, alpha = 0.f;
    if (bestF >= 0) {
        alpha = 1.f;
        const float4* I = g_ins + (size_t)(base + bestF) * 3;
        float rz0 = __ldg(I).w, rz1 = __ldg(I + 1).w, rz2 = __ldg(I + 2).w;
        float t0 = fminf(fmaxf((bw0 * 3.f) * (bestZ * rz0), 0.f), 2.999f);
        float t1 = fminf(fmaxf((bw1 * 3.f) * (bestZ * rz1), 0.f), 2.999f);
        float t2 = fminf(fmaxf((bw2 * 3.f) * (bestZ * rz2), 0.f), 2.999f);
        int l0 = (int)t0, l1 = (int)t1, l2 = (int)t2;
        float f0 = t0 - (float)l0, f1 = t1 - (float)l1, f2 = t2 - (float)l2;
        const float* tb = tex + (size_t)(base + bestF) * 192;  // 4*4*4*3
        #pragma unroll
        for (int pn = 0; pn < 8; pn++) {
            int b0 = pn & 1, b1 = (pn >> 1) & 1, b2 = (pn >> 2) & 1;
            float wc = (b0 ? f0 : 1.f - f0) * (b1 ? f1 : 1.f - f1) * (b2 ? f2 : 1.f - f2);
            const float* tp = tb + (size_t)((((l0 + b0) * 4 + (l1 + b1)) * 4 + (l2 + b2)) * 3);
            cr = fmaf(wc, __ldg(tp + 0), cr);
            cg = fmaf(wc, __ldg(tp + 1), cg);
            cb = fmaf(wc, __ldg(tp + 2), cb);
        }
    }

    // Output: [rgb (B,256,256,3)] [alpha (B,256,256)] [zp (B,256,256)]
    int p = i * IMG + j;
    size_t P = NPIX;
    float* orgb = out + ((size_t)b * P + p) * 3;
    orgb[0] = cr; orgb[1] = cg; orgb[2] = cb;
    out[(size_t)B * P * 3 + (size_t)b * P + p] = alpha;
    out[(size_t)B * P * 3 + (size_t)B * P + (size_t)b * P + p] = bestZ;
}

extern "C" void kernel_launch(void* const* d_in, const int* in_sizes, int n_in,
                              void* d_out, int out_size) {
    const float* faces = (const float*)d_in[0];   // (B,F,3,3) f32
    const float* tex   = (const float*)d_in[1];   // (B,F,4,4,4,3) f32
    float* out = (float*)d_out;

    int BF = in_sizes[0] / 9;
    int B  = out_size / (NPIX * 5);
    int F  = BF / B;

    prep_kernel<<<(BF + 255) / 256, 256>>>(faces, BF);
    dim3 grid(IMG / TILE, IMG / TILE, B);
    raster_kernel<<<grid, 512>>>(tex, out, F, B);
}

// round 15
// speedup vs baseline: 2.0683x; 1.0033x over previous
#include <cuda_runtime.h>
#include <cuda_bf16.h>

#define IMG   256
#define TILE  16
#define NPIX  (IMG*IMG)
#define FCAP  8192          // B*F = 2*4096 faces total
#define CCAP  2048          // per-tile candidate capacity
#define NEARP 0.1f
#define FARP  100.0f

// Per-face precomputed data (prep kernel -> raster kernel)
// g_edge[f*3+e] = (xa, ya, xb-xa, yb-ya) for edge e of face f
// g_ins [f*3+k] = (inv[k][0], inv[k][1], inv[k][2], 1/z_k)
// g_bbox[f]     = (xmin, xmax, ymin, ymax) conservative
// g_zmin[f]     = min(z0,z1,z2) — lower bound on zp anywhere on the face
__device__ float4 g_edge[FCAP*3];
__device__ float4 g_ins [FCAP*3];
__device__ float4 g_bbox[FCAP];
__device__ float  g_zmin[FCAP];

__global__ void prep_kernel(const float* __restrict__ faces, int BF) {
    int f = blockIdx.x * blockDim.x + threadIdx.x;
    if (f >= BF) return;
    const float* v = faces + (size_t)f * 9;
    float x0 = v[0], y0 = v[1], z0 = v[2];
    float x1 = v[3], y1 = v[4], z1 = v[5];
    float x2 = v[6], y2 = v[7], z2 = v[8];

    g_edge[f*3+0] = make_float4(x0, y0, x1 - x0, y1 - y0);
    g_edge[f*3+1] = make_float4(x1, y1, x2 - x1, y2 - y1);
    g_edge[f*3+2] = make_float4(x2, y2, x0 - x2, y0 - y2);

    // det exactly as reference, then clamp away from 0
    float det = x2*(y0 - y1) + x0*(y1 - y2) + x1*(y2 - y0);
    det = (det >= 0.f) ? fmaxf(det, 1e-10f) : fminf(det, -1e-10f);

    g_ins[f*3+0] = make_float4(__fdiv_rn(y1 - y2, det), __fdiv_rn(x2 - x1, det),
                               __fdiv_rn(x1*y2 - x2*y1, det), __frcp_rn(z0));
    g_ins[f*3+1] = make_float4(__fdiv_rn(y2 - y0, det), __fdiv_rn(x0 - x2, det),
                               __fdiv_rn(x2*y0 - x0*y2, det), __frcp_rn(z1));
    g_ins[f*3+2] = make_float4(__fdiv_rn(y0 - y1, det), __fdiv_rn(x1 - x0, det),
                               __fdiv_rn(x0*y1 - x1*y0, det), __frcp_rn(z2));

    float xmn = fminf(x0, fminf(x1, x2)) - 1e-4f;
    float xmx = fmaxf(x0, fmaxf(x1, x2)) + 1e-4f;
    float ymn = fminf(y0, fminf(y1, y2)) - 1e-4f;
    float ymx = fmaxf(y0, fmaxf(y1, y2)) + 1e-4f;
    g_bbox[f] = make_float4(xmn, xmx, ymn, ymx);
    g_zmin[f] = fminf(z0, fminf(z1, z2));
}

// Block = one 16x16 tile, 512 threads = (256 pixels) x (2 candidate subsets).
// Candidates are bbox-binned into smem as (zmin|faceid) keys, bitonic-sorted
// ascending, then scanned with per-lane early-z skip (zp >= zmin(face), so
// zmin > bestZ can never win — strict, so the index tie-break is unaffected)
// and a warp-wide break once every lane is converged. Winner selection is
// order-independent -> output bitwise identical to the unsorted scan.
__global__ __launch_bounds__(512)
void raster_kernel(const float* __restrict__ tex, float* __restrict__ out,
                   int F, int B) {
    __shared__ unsigned long long sKey[CCAP];
    __shared__ int   sCount;
    __shared__ float sZ [256];
    __shared__ int   sFc[256];
    __shared__ float sW0[256], sW1[256], sW2[256];

    int b  = blockIdx.z;
    int tx = blockIdx.x, ty = blockIdx.y;
    int tid = threadIdx.x;
    int pix = tid & 255;          // 0..255 pixel within tile
    int s   = tid >> 8;           // 0/1 candidate subset (uniform per warp)
    int j  = tx * TILE + (pix & 15);
    int i  = ty * TILE + (pix >> 4);

    float xp = (2.f * j + 1.f - IMG) * (1.f / IMG);
    float yp = -((2.f * i + 1.f - IMG) * (1.f / IMG));

    // Tile pixel-center extents for bbox culling
    float xlo = (2.f * (tx * TILE) + 1.f - IMG) * (1.f / IMG);
    float xhi = xlo + (2.f * (TILE - 1)) * (1.f / IMG);
    float yhi = -((2.f * (ty * TILE) + 1.f - IMG) * (1.f / IMG));
    float ylo = yhi - (2.f * (TILE - 1)) * (1.f / IMG);

    if (tid == 0) sCount = 0;
    __syncthreads();

    int base = b * F;
    // Bin: cull by bbox into smem keyed candidate list (zmin in high bits,
    // face id in low bits; z > 0 so float bits are order-preserving).
    for (int f = tid; f < F; f += 512) {
        float4 bb = g_bbox[base + f];
        if (bb.x <= xhi && bb.y >= xlo && bb.z <= yhi && bb.w >= ylo) {
            int pos = atomicAdd(&sCount, 1);
            if (pos < CCAP) {
                unsigned int zb = __float_as_uint(g_zmin[base + f]);
                sKey[pos] = ((unsigned long long)zb << 32) | (unsigned int)f;
            }
        }
    }
    __syncthreads();
    int nc = min(sCount, CCAP);

    // Pad to power of two and bitonic-sort ascending.
    int npad = 1;
    while (npad < nc) npad <<= 1;
    for (int k2 = nc + tid; k2 < npad; k2 += 512) sKey[k2] = ~0ull;
    __syncthreads();
    for (int k = 2; k <= npad; k <<= 1) {
        for (int jj = k >> 1; jj > 0; jj >>= 1) {
            for (int idx = tid; idx < npad; idx += 512) {
                int ixj = idx ^ jj;
                if (ixj > idx) {
                    unsigned long long a = sKey[idx], c2 = sKey[ixj];
                    bool up = ((idx & k) == 0);
                    if ((a > c2) == up) { sKey[idx] = c2; sKey[ixj] = a; }
                }
            }
            __syncthreads();
        }
    }

    float bestZ = FARP;
    int   bestF = -1;
    float bw0 = 0.f, bw1 = 0.f, bw2 = 0.f;

    for (int c = s; c < nc; c += 2) {
        unsigned long long key = sKey[c];
        float zminf = __uint_as_float((unsigned int)(key >> 32));
        // Sorted ascending: if every lane's bestZ is already below this
        // face's zmin, no remaining candidate can win for any lane.
        if (__all_sync(0xffffffffu, zminf > bestZ)) break;
        if (zminf <= bestZ) {
            int f = (int)(unsigned int)(key & 0xffffffffu);
            int idx3 = (base + f) * 3;
            const float4* E = g_edge + idx3;
            float4 e0 = __ldg(E), e1 = __ldg(E + 1), e2 = __ldg(E + 2);
            // edge = (yp-ya)*(xb-xa) - (xp-xa)*(yb-ya) — reference-shaped fmaf
            float v0 = fmaf(yp - e0.y, e0.z, -((xp - e0.x) * e0.w));
            float v1 = fmaf(yp - e1.y, e1.z, -((xp - e1.x) * e1.w));
            float v2 = fmaf(yp - e2.y, e2.z, -((xp - e2.x) * e2.w));
            if (v0 >= 0.f && v1 >= 0.f && v2 >= 0.f) {
                const float4* I = g_ins + idx3;
                float4 r0 = __ldg(I), r1 = __ldg(I + 1), r2 = __ldg(I + 2);
                float w0 = fmaf(r0.x, xp, fmaf(r0.y, yp, r0.z));
                float w1 = fmaf(r1.x, xp, fmaf(r1.y, yp, r1.z));
                float w2 = fmaf(r2.x, xp, fmaf(r2.y, yp, r2.z));
                w0 = fminf(fmaxf(w0, 0.f), 1.f);
                w1 = fminf(fmaxf(w1, 0.f), 1.f);
                w2 = fminf(fmaxf(w2, 0.f), 1.f);
                float rs = __frcp_rn(fmaxf((w0 + w1) + w2, 1e-10f));
                w0 *= rs; w1 *= rs; w2 *= rs;
                float izp = fmaf(w0, r0.w, fmaf(w1, r1.w, w2 * r2.w));
                float zp  = __frcp_rn(fmaxf(izp, 1e-10f));
                if (zp > NEARP && zp < FARP) {
                    if (zp < bestZ || (zp == bestZ && f < bestF)) {
                        bestZ = zp; bestF = f;
                        bw0 = w0; bw1 = w1; bw2 = w2;
                    }
                }
            }
        }
    }

    // Merge subset-1 partials into subset-0 threads (lexicographic (z, f)).
    if (s == 1) {
        sZ[pix] = bestZ; sFc[pix] = bestF;
        sW0[pix] = bw0; sW1[pix] = bw1; sW2[pix] = bw2;
    }
    __syncthreads();
    if (s == 1) return;

    {
        float z1 = sZ[pix]; int f1 = sFc[pix];
        if (z1 < bestZ || (z1 == bestZ && f1 >= 0 && (unsigned)f1 < (unsigned)bestF)) {
            bestZ = z1; bestF = f1;
            bw0 = sW0[pix]; bw1 = sW1[pix]; bw2 = sW2[pix];
        }
    }

    // Shade winner: trilinear sample of 4x4x4x3 texture
    float cr = 0.f, cg = 0.f, cb = 0.f, alpha = 0.f;
    if (bestF >= 0) {
        alpha = 1.f;
        const float4* I = g_ins + (size_t)(base + bestF) * 3;
        float rz0 = __ldg(I).w, rz1 = __ldg(I + 1).w, rz2 = __ldg(I + 2).w;
        float t0 = fminf(fmaxf((bw0 * 3.f) * (bestZ * rz0), 0.f), 2.999f);
        float t1 = fminf(fmaxf((bw1 * 3.f) * (bestZ * rz1), 0.f), 2.999f);
        float t2 = fminf(fmaxf((bw2 * 3.f) * (bestZ * rz2), 0.f), 2.999f);
        int l0 = (int)t0, l1 = (int)t1, l2 = (int)t2;
        float f0 = t0 - (float)l0, f1 = t1 - (float)l1, f2 = t2 - (float)l2;
        const float* tb = tex + (size_t)(base + bestF) * 192;  // 4*4*4*3
        #pragma unroll
        for (int pn = 0; pn < 8; pn++) {
            int b0 = pn & 1, b1 = (pn >> 1) & 1, b2 = (pn >> 2) & 1;
            float wc = (b0 ? f0 : 1.f - f0) * (b1 ? f1 : 1.f - f1) * (b2 ? f2 : 1.f - f2);
            const float* tp = tb + (size_t)((((l0 + b0) * 4 + (l1 + b1)) * 4 + (l2 + b2)) * 3);
            cr = fmaf(wc, __ldg(tp + 0), cr);
            cg = fmaf(wc, __ldg(tp + 1), cg);
            cb = fmaf(wc, __ldg(tp + 2), cb);
        }
    }

    // Output: [rgb (B,256,256,3)] [alpha (B,256,256)] [zp (B,256,256)]
    int p = i * IMG + j;
    size_t P = NPIX;
    float* orgb = out + ((size_t)b * P + p) * 3;
    orgb[0] = cr; orgb[1] = cg; orgb[2] = cb;
    out[(size_t)B * P * 3 + (size_t)b * P + p] = alpha;
    out[(size_t)B * P * 3 + (size_t)B * P + (size_t)b * P + p] = bestZ;
}

extern "C" void kernel_launch(void* const* d_in, const int* in_sizes, int n_in,
                              void* d_out, int out_size) {
    const float* faces = (const float*)d_in[0];   // (B,F,3,3) f32
    const float* tex   = (const float*)d_in[1];   // (B,F,4,4,4,3) f32
    float* out = (float*)d_out;

    int BF = in_sizes[0] / 9;
    int B  = out_size / (NPIX * 5);
    int F  = BF / B;

    prep_kernel<<<(BF + 255) / 256, 256>>>(faces, BF);
    dim3 grid(IMG / TILE, IMG / TILE, B);
    raster_kernel<<<grid, 512>>>(tex, out, F, B);
}